// round 3
// baseline (speedup 1.0000x reference)
#include <cuda_runtime.h>

typedef unsigned long long u64;

#define B_SZ   16
#define N_SEQ  2048
#define F_DIM  256
#define BNR    (B_SZ * N_SEQ)   // 32768 rows

// ---------------- device scratch (no runtime allocation allowed) ----------------
__device__ float g_h[(size_t)BNR * F_DIM];                 // 33.5 MB
__device__ float g_q[(size_t)BNR * F_DIM];                 // also reused as R temp
__device__ float g_k[(size_t)BNR * F_DIM];
__device__ float g_v[(size_t)BNR * F_DIM];
__device__ float g_s[(size_t)B_SZ * N_SEQ * N_SEQ];        // 268 MB scores

// ---------------- packed f32x2 helpers (Blackwell 2xFP32 path) ----------------
__device__ __forceinline__ u64 dupf(float x) {
    u64 r; unsigned xi = __float_as_uint(x);
    asm("mov.b64 %0, {%1,%1};" : "=l"(r) : "r"(xi));
    return r;
}
__device__ __forceinline__ void ffma2(u64& d, u64 a, u64 b) {
    asm("fma.rn.f32x2 %0, %1, %2, %0;" : "+l"(d) : "l"(a), "l"(b));
}
__device__ __forceinline__ float f2lo(u64 v) { return __uint_as_float((unsigned)v); }
__device__ __forceinline__ float f2hi(u64 v) { return __uint_as_float((unsigned)(v >> 32)); }

// ---------------- positional encoder stage 1: R = relu(p @ W1^T + b1) ----------------
__global__ void pos_kernel(const float* __restrict__ p, const float* __restrict__ W1,
                           const float* __restrict__ b1, float* __restrict__ R) {
    int idx = blockIdx.x * blockDim.x + threadIdx.x;   // over BNR * F_DIM
    int i = idx >> 8;          // row (F_DIM = 256)
    int f = idx & 255;
    float p0 = __ldg(p + (size_t)i * 3 + 0);
    float p1 = __ldg(p + (size_t)i * 3 + 1);
    float p2 = __ldg(p + (size_t)i * 3 + 2);
    float w0 = __ldg(W1 + f * 3 + 0);
    float w1 = __ldg(W1 + f * 3 + 1);
    float w2 = __ldg(W1 + f * 3 + 2);
    float r = fmaf(p0, w0, fmaf(p1, w1, fmaf(p2, w2, __ldg(b1 + f))));
    R[idx] = fmaxf(r, 0.0f);
}

// ---------------- generic tiled GEMM ----------------
// C[m][n] = alpha * sum_k A[m][k] * B(k,n)  (+ bias[n]) (+ addm[m][n])
// B_IS_NT:  B stored [N, K] row-major (k contiguous)  -> C = A * B^T
// !B_IS_NT: B stored [K, N] row-major (n contiguous)  -> C = A * B
#define BM 128
#define BN 64
#define BK 16
#define NT 256

template<bool B_IS_NT, bool HAS_BIAS, bool HAS_ADD>
__global__ void __launch_bounds__(NT, 2) gemm_kernel(
    const float* __restrict__ Ag, const float* __restrict__ Bg, float* __restrict__ Cg,
    const float* __restrict__ bias, const float* __restrict__ addg,
    int M, int N, int K, size_t sA, size_t sB, size_t sC, float alpha)
{
    const float* A = Ag + (size_t)blockIdx.z * sA;
    const float* Bm = Bg + (size_t)blockIdx.z * sB;
    float*       C  = Cg + (size_t)blockIdx.z * sC;
    const float* Xm = HAS_ADD ? (addg + (size_t)blockIdx.z * sC) : nullptr;

    __shared__ float As[BK][BM];   // transposed A tile: As[k][m]
    __shared__ float Bs[BK][BN];   // Bs[k][n]

    const int tid = threadIdx.x;
    const int tx = tid & 15;       // 0..15  -> n micro (4 cols)
    const int ty = tid >> 4;       // 0..15  -> m micro (8 rows)
    const int row0 = blockIdx.y * BM;
    const int col0 = blockIdx.x * BN;

    // global load mappings
    const int ar = tid >> 2;           // 0..63 (A row within tile; +64 for second half)
    const int ac = (tid & 3) * 4;      // k sub-offset
    int br, bc;
    if (B_IS_NT) { br = tid >> 2; bc = (tid & 3) * 4; }     // n-row, k-col
    else         { br = tid >> 4; bc = (tid & 15) * 4; }    // k-row, n-col

    u64 acc[4][4];
#pragma unroll
    for (int i = 0; i < 4; i++)
#pragma unroll
        for (int j = 0; j < 4; j++) acc[i][j] = 0ull;

    float4 ra0, ra1, rb;
    {   // prologue: stage k-chunk 0
        const float* Ab = A + (size_t)(row0 + ar) * K + ac;
        ra0 = *(const float4*)Ab;
        ra1 = *(const float4*)(Ab + (size_t)64 * K);
        if (B_IS_NT) rb = *(const float4*)(Bm + (size_t)(col0 + br) * K + bc);
        else         rb = *(const float4*)(Bm + (size_t)br * N + col0 + bc);
    }

    for (int kc = 0; kc < K; kc += BK) {
        // commit staged regs to smem
        As[ac + 0][ar]      = ra0.x; As[ac + 1][ar]      = ra0.y;
        As[ac + 2][ar]      = ra0.z; As[ac + 3][ar]      = ra0.w;
        As[ac + 0][ar + 64] = ra1.x; As[ac + 1][ar + 64] = ra1.y;
        As[ac + 2][ar + 64] = ra1.z; As[ac + 3][ar + 64] = ra1.w;
        if (B_IS_NT) {
            Bs[bc + 0][br] = rb.x; Bs[bc + 1][br] = rb.y;
            Bs[bc + 2][br] = rb.z; Bs[bc + 3][br] = rb.w;
        } else {
            *(float4*)&Bs[br][bc] = rb;
        }
        __syncthreads();

        const int kn = kc + BK;
        if (kn < K) {   // prefetch next chunk while computing
            const float* Ab = A + (size_t)(row0 + ar) * K + kn + ac;
            ra0 = *(const float4*)Ab;
            ra1 = *(const float4*)(Ab + (size_t)64 * K);
            if (B_IS_NT) rb = *(const float4*)(Bm + (size_t)(col0 + br) * K + kn + bc);
            else         rb = *(const float4*)(Bm + (size_t)(kn + br) * N + col0 + bc);
        }

#pragma unroll
        for (int kk = 0; kk < BK; kk++) {
            const ulonglong2* ap = (const ulonglong2*)&As[kk][ty * 8];
            ulonglong2 av0 = ap[0], av1 = ap[1];
            u64 a0 = av0.x, a1 = av0.y, a2 = av1.x, a3 = av1.y;
            float4 bf = *(const float4*)&Bs[kk][tx * 4];
            u64 b0 = dupf(bf.x), b1 = dupf(bf.y), b2 = dupf(bf.z), b3 = dupf(bf.w);
            ffma2(acc[0][0], a0, b0); ffma2(acc[0][1], a0, b1);
            ffma2(acc[0][2], a0, b2); ffma2(acc[0][3], a0, b3);
            ffma2(acc[1][0], a1, b0); ffma2(acc[1][1], a1, b1);
            ffma2(acc[1][2], a1, b2); ffma2(acc[1][3], a1, b3);
            ffma2(acc[2][0], a2, b0); ffma2(acc[2][1], a2, b1);
            ffma2(acc[2][2], a2, b2); ffma2(acc[2][3], a2, b3);
            ffma2(acc[3][0], a3, b0); ffma2(acc[3][1], a3, b1);
            ffma2(acc[3][2], a3, b2); ffma2(acc[3][3], a3, b3);
        }
        __syncthreads();
    }

    // epilogue
    float4 bv = make_float4(0.f, 0.f, 0.f, 0.f);
    if (HAS_BIAS) bv = *(const float4*)&bias[col0 + tx * 4];
#pragma unroll
    for (int i = 0; i < 4; i++) {
        const int r0 = row0 + ty * 8 + 2 * i;
        float4 olo, ohi;
        olo.x = f2lo(acc[i][0]) * alpha + bv.x;
        olo.y = f2lo(acc[i][1]) * alpha + bv.y;
        olo.z = f2lo(acc[i][2]) * alpha + bv.z;
        olo.w = f2lo(acc[i][3]) * alpha + bv.w;
        ohi.x = f2hi(acc[i][0]) * alpha + bv.x;
        ohi.y = f2hi(acc[i][1]) * alpha + bv.y;
        ohi.z = f2hi(acc[i][2]) * alpha + bv.z;
        ohi.w = f2hi(acc[i][3]) * alpha + bv.w;
        if (HAS_ADD) {
            float4 x0 = *(const float4*)&Xm[(size_t)r0 * N + col0 + tx * 4];
            float4 x1 = *(const float4*)&Xm[(size_t)(r0 + 1) * N + col0 + tx * 4];
            olo.x += x0.x; olo.y += x0.y; olo.z += x0.z; olo.w += x0.w;
            ohi.x += x1.x; ohi.y += x1.y; ohi.z += x1.z; ohi.w += x1.w;
        }
        *(float4*)&C[(size_t)r0 * N + col0 + tx * 4]       = olo;
        *(float4*)&C[(size_t)(r0 + 1) * N + col0 + tx * 4] = ohi;
    }
}

// ---------------- rowwise softmax over N_SEQ = 2048 (one block per row) ----------------
__global__ void softmax_kernel(float* __restrict__ S) {
    __shared__ float red[8];
    const size_t row = blockIdx.x;
    float4* r = (float4*)(S + row * (size_t)N_SEQ);
    const int tid = threadIdx.x;        // 256 threads, 8 floats each
    float4 v0 = r[tid * 2], v1 = r[tid * 2 + 1];

    float m = fmaxf(fmaxf(fmaxf(v0.x, v0.y), fmaxf(v0.z, v0.w)),
                    fmaxf(fmaxf(v1.x, v1.y), fmaxf(v1.z, v1.w)));
#pragma unroll
    for (int o = 16; o; o >>= 1) m = fmaxf(m, __shfl_xor_sync(0xffffffffu, m, o));
    if ((tid & 31) == 0) red[tid >> 5] = m;
    __syncthreads();
    float mm = red[0];
#pragma unroll
    for (int i = 1; i < 8; i++) mm = fmaxf(mm, red[i]);
    __syncthreads();   // before red reuse

    v0.x = __expf(v0.x - mm); v0.y = __expf(v0.y - mm);
    v0.z = __expf(v0.z - mm); v0.w = __expf(v0.w - mm);
    v1.x = __expf(v1.x - mm); v1.y = __expf(v1.y - mm);
    v1.z = __expf(v1.z - mm); v1.w = __expf(v1.w - mm);

    float s = ((v0.x + v0.y) + (v0.z + v0.w)) + ((v1.x + v1.y) + (v1.z + v1.w));
#pragma unroll
    for (int o = 16; o; o >>= 1) s += __shfl_xor_sync(0xffffffffu, s, o);
    if ((tid & 31) == 0) red[tid >> 5] = s;
    __syncthreads();
    float tot = ((red[0] + red[1]) + (red[2] + red[3])) +
                ((red[4] + red[5]) + (red[6] + red[7]));
    float inv = __frcp_rn(tot);

    v0.x *= inv; v0.y *= inv; v0.z *= inv; v0.w *= inv;
    v1.x *= inv; v1.y *= inv; v1.z *= inv; v1.w *= inv;
    r[tid * 2] = v0; r[tid * 2 + 1] = v1;
}

// ---------------- launch ----------------
extern "C" void kernel_launch(void* const* d_in, const int* in_sizes, int n_in,
                              void* d_out, int out_size) {
    const float* x  = (const float*)d_in[0];
    const float* p  = (const float*)d_in[1];
    const float* Wq = (const float*)d_in[2];
    const float* bq = (const float*)d_in[3];
    const float* Wk = (const float*)d_in[4];
    const float* bk = (const float*)d_in[5];
    const float* Wv = (const float*)d_in[6];
    const float* bv = (const float*)d_in[7];
    const float* W1 = (const float*)d_in[8];
    const float* b1 = (const float*)d_in[9];
    const float* W2 = (const float*)d_in[10];
    const float* b2 = (const float*)d_in[11];
    float* out = (float*)d_out;

    float *hbuf, *qbuf, *kbuf, *vbuf, *sbuf;
    cudaGetSymbolAddress((void**)&hbuf, g_h);
    cudaGetSymbolAddress((void**)&qbuf, g_q);
    cudaGetSymbolAddress((void**)&kbuf, g_k);
    cudaGetSymbolAddress((void**)&vbuf, g_v);
    cudaGetSymbolAddress((void**)&sbuf, g_s);

    // 1) R = relu(p @ W1^T + b1)   (R temporarily in g_q)
    pos_kernel<<<(BNR * F_DIM) / 256, 256>>>(p, W1, b1, qbuf);

    // 2) H = R @ W2^T + b2 + x
    gemm_kernel<true, true, true><<<dim3(F_DIM / BN, BNR / BM, 1), NT>>>(
        qbuf, W2, hbuf, b2, x, BNR, F_DIM, F_DIM, 0, 0, 0, 1.0f);

    // 3) QKV projections (note the reference swaps: q uses Wk/bk, k uses Wq/bq)
    gemm_kernel<true, true, false><<<dim3(F_DIM / BN, BNR / BM, 1), NT>>>(
        hbuf, Wk, qbuf, bk, nullptr, BNR, F_DIM, F_DIM, 0, 0, 0, 1.0f);
    gemm_kernel<true, true, false><<<dim3(F_DIM / BN, BNR / BM, 1), NT>>>(
        hbuf, Wq, kbuf, bq, nullptr, BNR, F_DIM, F_DIM, 0, 0, 0, 1.0f);
    gemm_kernel<true, true, false><<<dim3(F_DIM / BN, BNR / BM, 1), NT>>>(
        hbuf, Wv, vbuf, bv, nullptr, BNR, F_DIM, F_DIM, 0, 0, 0, 1.0f);

    // 4) S[b] = (Q[b] @ K[b]^T) / 16
    gemm_kernel<true, false, false><<<dim3(N_SEQ / BN, N_SEQ / BM, B_SZ), NT>>>(
        qbuf, kbuf, sbuf, nullptr, nullptr, N_SEQ, N_SEQ, F_DIM,
        (size_t)N_SEQ * F_DIM, (size_t)N_SEQ * F_DIM, (size_t)N_SEQ * N_SEQ, 0.0625f);

    // 5) rowwise softmax
    softmax_kernel<<<B_SZ * N_SEQ, 256>>>(sbuf);

    // 6) out[b] = P[b] @ V[b]
    gemm_kernel<false, false, false><<<dim3(F_DIM / BN, N_SEQ / BM, B_SZ), NT>>>(
        sbuf, vbuf, out, nullptr, nullptr, N_SEQ, F_DIM, N_SEQ,
        (size_t)N_SEQ * N_SEQ, (size_t)N_SEQ * F_DIM, (size_t)N_SEQ * F_DIM, 1.0f);
}